// round 6
// baseline (speedup 1.0000x reference)
#include <cuda_runtime.h>
#include <cuda_bf16.h>
#include <cstdint>

#define T_LEN 32768
#define HID   256
#define NI_   1024
#define OUT_  32
#define HSTR  1056   // padded h-buffer stride in bytes (512 + 16 pad + 512 + 16)

// ---------------- scratch (device globals: no allocation allowed) ----------------
__device__ float g_xg_f[(size_t)T_LEN * 1024];
__device__ float g_xg_b[(size_t)T_LEN * 1024];
__device__ float g_h0[(size_t)T_LEN * 512];
__device__ float g_h1[(size_t)T_LEN * 512];

// ---------------- device helpers ----------------
__device__ __forceinline__ unsigned long long ffma2(unsigned long long a,
                                                    unsigned long long b,
                                                    unsigned long long c) {
    unsigned long long d;
    asm("fma.rn.f32x2 %0, %1, %2, %3;" : "=l"(d) : "l"(a), "l"(b), "l"(c));
    return d;
}

__device__ __forceinline__ uint32_t smaddr(const void* p) {
    return (uint32_t)__cvta_generic_to_shared(p);
}
__device__ __forceinline__ void mbar_init(uint32_t a, uint32_t cnt) {
    asm volatile("mbarrier.init.shared.b64 [%0], %1;" :: "r"(a), "r"(cnt) : "memory");
}
__device__ __forceinline__ uint32_t mapa_sh(uint32_t a, uint32_t rank) {
    uint32_t r;
    asm("mapa.shared::cluster.u32 %0, %1, %2;" : "=r"(r) : "r"(a), "r"(rank));
    return r;
}
__device__ __forceinline__ uint32_t mbar_try_acq(uint32_t addr, uint32_t parity) {
    uint32_t done;
    asm volatile(
        "{\n\t.reg .pred P;\n\t"
        "mbarrier.try_wait.parity.acquire.cluster.shared::cta.b64 P, [%1], %2;\n\t"
        "selp.u32 %0, 1, 0, P;\n\t}"
        : "=r"(done) : "r"(addr), "r"(parity) : "memory");
    return done;
}
__device__ __forceinline__ void cluster_sync_() {
    asm volatile("barrier.cluster.arrive.aligned;" ::: "memory");
    asm volatile("barrier.cluster.wait.aligned;" ::: "memory");
}

// =================================================================================
// Kernel 1: layer-0 input projection. xg[t][row] = x[t] . w_ih[row] + b_ih + b_hh
// =================================================================================
__global__ void __launch_bounds__(256) xg0_kernel(
    const float* __restrict__ Y, const float* __restrict__ dT,
    const float* __restrict__ w_f, const float* __restrict__ bi_f, const float* __restrict__ bh_f,
    const float* __restrict__ w_b, const float* __restrict__ bi_b, const float* __restrict__ bh_b,
    float* __restrict__ out_f, float* __restrict__ out_b)
{
    __shared__ float xs[32][64];
    __shared__ float ws[64][128];
    const float* w  = blockIdx.z ? w_b  : w_f;
    const float* bi = blockIdx.z ? bi_b : bi_f;
    const float* bh = blockIdx.z ? bh_b : bh_f;
    float* out      = blockIdx.z ? out_b : out_f;

    const int tid = threadIdx.x;
    const int tbase = blockIdx.y * 32;
    const int cbase = blockIdx.x * 128;

    for (int i = tid; i < 32 * 64; i += 256) {
        int tt = i >> 6, k = i & 63;
        int t = tbase + tt;
        xs[tt][k] = (k < 63) ? Y[(size_t)t * 63 + k] : dT[t];
    }
    for (int i = tid; i < 128 * 64; i += 256) {
        int c = i >> 6, k = i & 63;
        ws[k][c] = w[(size_t)(cbase + c) * 64 + k];
    }
    __syncthreads();

    const int c = tid & 127;
    const int tr0 = tid >> 7;
    const float bias = bi[cbase + c] + bh[cbase + c];
    for (int tt = tr0; tt < 32; tt += 2) {
        float acc = bias;
        #pragma unroll
        for (int k = 0; k < 64; k++) acc += xs[tt][k] * ws[k][c];
        out[(size_t)(tbase + tt) * 1024 + cbase + c] = acc;
    }
}

// =================================================================================
// Kernel 2: LSTM scan v3. 8-CTA cluster per direction (2 clusters, grid 16).
// Warp w of CTA `rank` owns units [rank*32 + 4w, +4) with ALL 4 gate rows:
// pair q=lane>>1 -> gate g=q>>2, unit u=q&3, row = g*256 + rank*32 + 4w + u.
// Step: 8-lane mbar wait (one mbar per source CTA) -> conflict-free MAC vs padded
// SMEM h -> pair shfl-reduce -> intra-warp gate gather -> lanes0-3 compute c/h ->
// lane0 sends 16-B chunk to all 8 CTAs (v4.b32) + release-arrive per peer.
// No __syncthreads in the steady-state loop.
// =================================================================================
__global__ void __launch_bounds__(256, 1) lstm_scan_kernel(
    const float* __restrict__ xg_f, const float* __restrict__ xg_b,
    const float* __restrict__ whh_f, const float* __restrict__ whh_b,
    float* __restrict__ h_out)
{
    __shared__ __align__(16) unsigned char h_raw[2 * HSTR];  // padded, double buffered
    __shared__ unsigned long long mbars[16];                 // [buf][src]

    const int tid  = threadIdx.x;
    const int lane = tid & 31;
    const int wid  = tid >> 5;
    const int rank = blockIdx.x & 7;
    const int dir  = blockIdx.x >> 3;
    const float* xg  = dir ? xg_b  : xg_f;
    const float* whh = dir ? whh_b : whh_f;
    const int unit_base = rank * 32;

    const int q    = lane >> 1;      // pair 0..15
    const int half = lane & 1;
    const int gate = q >> 2;         // 0..3 (i,f,g,o)
    const int u    = q & 3;          // unit within warp
    const int row  = gate * 256 + unit_base + 4 * wid + u;

    // Load this thread's 128 weights (half row) as 64 f32x2 pairs.
    unsigned long long w[64];
    {
        const ulonglong2* wg = (const ulonglong2*)(whh + (size_t)row * 256 + half * 128);
        #pragma unroll
        for (int i = 0; i < 32; i++) {
            ulonglong2 v = wg[i];
            w[2 * i] = v.x; w[2 * i + 1] = v.y;
        }
    }

    // init h buffers (zeros) + mbars
    for (int i = tid; i < 2 * HSTR / 4; i += 256) ((uint32_t*)h_raw)[i] = 0u;
    if (tid < 16) mbar_init(smaddr(&mbars[tid]), 8);   // 8 arrivals = 8 warps of one src CTA
    __syncthreads();
    cluster_sync_();

    const uint32_t hb      = smaddr(h_raw);
    const uint32_t mb_base = smaddr(&mbars[0]);

    // chunk byte offset of this warp's 4 units inside the padded h layout
    const int ub4 = unit_base + 4 * wid;                 // first unit (float index)
    const uint32_t chunk_off = (ub4 < 128) ? (uint32_t)(ub4 * 4)
                                           : (uint32_t)(528 + (ub4 - 128) * 4);

    // peer addresses (used by lane 0): h chunk + mbar[.][rank] for each dest CTA
    uint32_t peer_h[8], peer_mb[8];
    #pragma unroll
    for (int r = 0; r < 8; r++) {
        peer_h[r]  = mapa_sh(hb, (uint32_t)r) + chunk_off;
        peer_mb[r] = mapa_sh(mb_base, (uint32_t)r) + (uint32_t)rank * 8u;
    }

    // this warp's wait slot: lane l < 8 polls mbar[buf][l]
    const uint32_t my_mb = mb_base + (uint32_t)(lane & 7) * 8u;

    // reader base: half 0 at +0, half 1 at +528 (different bank group -> conflict-free)
    const uint32_t rd_base = hb + (half ? 528u : 0u);

    const int t0 = dir ? (T_LEN - 1) : 0;
    const int dt = dir ? -1 : 1;

    float c_state = 0.f;   // valid in lanes 0..3 (unit = lane)
    float xg_cur = 0.f, xg_nxt = 0.f;
    if (!half) {
        xg_cur = __ldg(&xg[(size_t)t0 * 1024 + row]);
        xg_nxt = __ldg(&xg[(size_t)(t0 + dt) * 1024 + row]);
    }
    int ph0 = 0, ph1 = 0;

    for (int s = 0; s < T_LEN; s++) {
        const int t = t0 + s * dt;
        const int buf = s & 1;
        const int nb  = buf ^ 1;

        // prefetch xg for step s+2 before blocking
        float xg_n2 = 0.f;
        if (!half && (s + 2 < T_LEN))
            xg_n2 = __ldg(&xg[(size_t)(t + 2 * dt) * 1024 + row]);

        if (s > 0) {
            const uint32_t par = (uint32_t)(buf ? ph1 : ph0);
            const uint32_t mba = my_mb + (uint32_t)buf * 64u;
            unsigned pend = (lane < 8) ? 1u : 0u;
            while (__any_sync(0xffffffffu, pend)) {
                if (pend) pend = !mbar_try_acq(mba, par);
            }
            __syncwarp();   // fence: all lanes' reads ordered after the acquires
            if (buf) ph1 ^= 1; else ph0 ^= 1;
        }

        // MAC: 32 conflict-free LDS.128 + 64 FFMA2, 4 accumulator chains
        const uint32_t ra = rd_base + (uint32_t)buf * (uint32_t)HSTR;
        unsigned long long acc0 = 0ULL, acc1 = 0ULL, acc2 = 0ULL, acc3 = 0ULL;
        #pragma unroll
        for (int i = 0; i < 16; i++) {
            unsigned long long hx, hy, hx2, hy2;
            asm("ld.shared.v2.u64 {%0,%1}, [%2];" : "=l"(hx), "=l"(hy) : "r"(ra + 32u * i));
            asm("ld.shared.v2.u64 {%0,%1}, [%2];" : "=l"(hx2), "=l"(hy2) : "r"(ra + 32u * i + 16u));
            acc0 = ffma2(w[4 * i + 0], hx,  acc0);
            acc1 = ffma2(w[4 * i + 1], hy,  acc1);
            acc2 = ffma2(w[4 * i + 2], hx2, acc2);
            acc3 = ffma2(w[4 * i + 3], hy2, acc3);
        }
        float2 a0 = *(float2*)&acc0, a1 = *(float2*)&acc1;
        float2 a2 = *(float2*)&acc2, a3 = *(float2*)&acc3;
        float sum = ((a0.x + a0.y) + (a1.x + a1.y)) + ((a2.x + a2.y) + (a3.x + a3.y));
        sum += __shfl_xor_sync(0xffffffffu, sum, 1);   // combine halves of the row
        if (!half) sum += xg_cur;                       // full preact now on even lanes

        // gather the 4 gate preacts of unit (lane&3) from even lanes
        const int uu = lane & 3;
        float iv = __shfl_sync(0xffffffffu, sum, 2 * uu);
        float fv = __shfl_sync(0xffffffffu, sum, 8 + 2 * uu);
        float gv = __shfl_sync(0xffffffffu, sum, 16 + 2 * uu);
        float ov = __shfl_sync(0xffffffffu, sum, 24 + 2 * uu);

        // gates (meaningful in lanes 0..3; other lanes compute harmless duplicates)
        float ei = __expf(-iv), ef = __expf(-fv), eo = __expf(-ov);
        float eg = __expf(-2.f * fabsf(gv));
        float si = __fdividef(1.f, 1.f + ei);
        float sf = __fdividef(1.f, 1.f + ef);
        float so = __fdividef(1.f, 1.f + eo);
        float tg = copysignf(__fdividef(1.f - eg, 1.f + eg), gv);
        c_state = sf * c_state + si * tg;
        float ec = __expf(-2.f * fabsf(c_state));
        float tc = copysignf(__fdividef(1.f - ec, 1.f + ec), c_state);
        float h = so * tc;

        // gather this warp's 4 h values for the 16-B chunk send
        uint32_t v0 = __shfl_sync(0xffffffffu, __float_as_uint(h), 0);
        uint32_t v1 = __shfl_sync(0xffffffffu, __float_as_uint(h), 1);
        uint32_t v2 = __shfl_sync(0xffffffffu, __float_as_uint(h), 2);
        uint32_t v3 = __shfl_sync(0xffffffffu, __float_as_uint(h), 3);

        if (lane == 0) {
            const uint32_t boff = (uint32_t)nb * (uint32_t)HSTR;
            #pragma unroll
            for (int r = 0; r < 8; r++) {
                asm volatile("st.shared::cluster.v4.b32 [%0], {%1,%2,%3,%4};"
                             :: "r"(peer_h[r] + boff), "r"(v0), "r"(v1), "r"(v2), "r"(v3)
                             : "memory");
                asm volatile("mbarrier.arrive.release.cluster.shared::cluster.b64 _, [%0];"
                             :: "r"(peer_mb[r] + (uint32_t)nb * 64u) : "memory");
            }
        }

        if (lane < 4)
            h_out[(size_t)t * 512 + dir * 256 + ub4 + lane] = h;

        xg_cur = xg_nxt;
        xg_nxt = xg_n2;
    }
    cluster_sync_();   // don't exit while peers' remote stores may target our SMEM
}

// =================================================================================
// Kernel 3: layer-1 input projection GEMM. BM=64, BN=64, BK=16, 256 threads.
// =================================================================================
__global__ void __launch_bounds__(256) xg1_gemm(
    const float* __restrict__ A,
    const float* __restrict__ Wf, const float* __restrict__ Wb,
    const float* __restrict__ bif, const float* __restrict__ bhf,
    const float* __restrict__ bib, const float* __restrict__ bhb,
    float* __restrict__ outf, float* __restrict__ outb)
{
    const float* W  = blockIdx.z ? Wb  : Wf;
    const float* bi = blockIdx.z ? bib : bif;
    const float* bh = blockIdx.z ? bhb : bhf;
    float* out      = blockIdx.z ? outb : outf;

    __shared__ float As[16][68];
    __shared__ float Bs[16][68];

    const int tid = threadIdx.x;
    const int tm = blockIdx.y * 64;
    const int cn = blockIdx.x * 64;
    const int tx = tid & 15;
    const int ty = tid >> 4;

    const int la_t = tid >> 2;
    const int la_k = (tid & 3) * 4;

    float acc[4][4] = {};

    for (int k0 = 0; k0 < 512; k0 += 16) {
        float4 av = *(const float4*)&A[(size_t)(tm + la_t) * 512 + k0 + la_k];
        float4 wv = *(const float4*)&W[(size_t)(cn + la_t) * 512 + k0 + la_k];
        __syncthreads();
        As[la_k + 0][la_t] = av.x; As[la_k + 1][la_t] = av.y;
        As[la_k + 2][la_t] = av.z; As[la_k + 3][la_t] = av.w;
        Bs[la_k + 0][la_t] = wv.x; Bs[la_k + 1][la_t] = wv.y;
        Bs[la_k + 2][la_t] = wv.z; Bs[la_k + 3][la_t] = wv.w;
        __syncthreads();
        #pragma unroll
        for (int k = 0; k < 16; k++) {
            float a[4], b[4];
            #pragma unroll
            for (int i = 0; i < 4; i++) a[i] = As[k][ty * 4 + i];
            #pragma unroll
            for (int j = 0; j < 4; j++) b[j] = Bs[k][tx * 4 + j];
            #pragma unroll
            for (int i = 0; i < 4; i++)
                #pragma unroll
                for (int j = 0; j < 4; j++)
                    acc[i][j] += a[i] * b[j];
        }
    }

    float bias[4];
    #pragma unroll
    for (int j = 0; j < 4; j++)
        bias[j] = bi[cn + tx * 4 + j] + bh[cn + tx * 4 + j];
    #pragma unroll
    for (int i = 0; i < 4; i++)
        #pragma unroll
        for (int j = 0; j < 4; j++)
            out[(size_t)(tm + ty * 4 + i) * 1024 + cn + tx * 4 + j] = acc[i][j] + bias[j];
}

// =================================================================================
// Kernel 4: FC at inducing points + split output.
// =================================================================================
__global__ void __launch_bounds__(64) fc_gather_kernel(
    const float* __restrict__ h1, const int* __restrict__ idx,
    const float* __restrict__ fc, float* __restrict__ out)
{
    __shared__ float hrow[512];
    const int b = blockIdx.x;
    const int t = idx[b];
    const int tid = threadIdx.x;
    for (int i = tid; i < 512; i += 64) hrow[i] = h1[(size_t)t * 512 + i];
    __syncthreads();
    float acc = 0.f;
    #pragma unroll 8
    for (int k = 0; k < 512; k++) acc += hrow[k] * fc[(size_t)k * 64 + tid];
    if (tid < 32) out[b * 32 + tid] = acc;
    else          out[NI_ * OUT_ + b * 32 + (tid - 32)] = acc;
}

// =================================================================================
// Launch
// =================================================================================
extern "C" void kernel_launch(void* const* d_in, const int* in_sizes, int n_in,
                              void* d_out, int out_size) {
    const float* Y        = (const float*)d_in[0];
    const float* dT       = (const float*)d_in[1];
    const int*   induce   = (const int*)  d_in[2];
    const float* w_ih_l0f = (const float*)d_in[3];
    const float* w_hh_l0f = (const float*)d_in[4];
    const float* b_ih_l0f = (const float*)d_in[5];
    const float* b_hh_l0f = (const float*)d_in[6];
    const float* w_ih_l0b = (const float*)d_in[7];
    const float* w_hh_l0b = (const float*)d_in[8];
    const float* b_ih_l0b = (const float*)d_in[9];
    const float* b_hh_l0b = (const float*)d_in[10];
    const float* w_ih_l1f = (const float*)d_in[11];
    const float* w_hh_l1f = (const float*)d_in[12];
    const float* b_ih_l1f = (const float*)d_in[13];
    const float* b_hh_l1f = (const float*)d_in[14];
    const float* w_ih_l1b = (const float*)d_in[15];
    const float* w_hh_l1b = (const float*)d_in[16];
    const float* b_ih_l1b = (const float*)d_in[17];
    const float* b_hh_l1b = (const float*)d_in[18];
    const float* fc_w     = (const float*)d_in[19];
    float* out = (float*)d_out;

    float *xg_f, *xg_b, *h0, *h1;
    cudaGetSymbolAddress((void**)&xg_f, g_xg_f);
    cudaGetSymbolAddress((void**)&xg_b, g_xg_b);
    cudaGetSymbolAddress((void**)&h0, g_h0);
    cudaGetSymbolAddress((void**)&h1, g_h1);

    // 1) layer-0 gate preactivations
    xg0_kernel<<<dim3(8, T_LEN / 32, 2), 256>>>(
        Y, dT,
        w_ih_l0f, b_ih_l0f, b_hh_l0f,
        w_ih_l0b, b_ih_l0b, b_hh_l0b,
        xg_f, xg_b);

    // cluster launch config for the scan
    cudaLaunchConfig_t cfg = {};
    cfg.gridDim  = dim3(16, 1, 1);
    cfg.blockDim = dim3(256, 1, 1);
    cfg.dynamicSmemBytes = 0;
    cfg.stream = 0;
    cudaLaunchAttribute attr[1];
    attr[0].id = cudaLaunchAttributeClusterDimension;
    attr[0].val.clusterDim.x = 8;
    attr[0].val.clusterDim.y = 1;
    attr[0].val.clusterDim.z = 1;
    cfg.attrs = attr;
    cfg.numAttrs = 1;

    // 2) layer-0 scan
    cudaLaunchKernelEx(&cfg, lstm_scan_kernel,
                       (const float*)xg_f, (const float*)xg_b,
                       w_hh_l0f, w_hh_l0b, h0);

    // 3) layer-1 gate preactivations (reuse xg buffers)
    xg1_gemm<<<dim3(16, T_LEN / 64, 2), 256>>>(
        (const float*)h0,
        w_ih_l1f, w_ih_l1b,
        b_ih_l1f, b_hh_l1f, b_ih_l1b, b_hh_l1b,
        xg_f, xg_b);

    // 4) layer-1 scan
    cudaLaunchKernelEx(&cfg, lstm_scan_kernel,
                       (const float*)xg_f, (const float*)xg_b,
                       w_hh_l1f, w_hh_l1b, h1);

    // 5) FC + gather
    fc_gather_kernel<<<NI_, 64>>>((const float*)h1, induce, fc_w, out);
}

// round 7
// speedup vs baseline: 2.3703x; 2.3703x over previous
#include <cuda_runtime.h>
#include <cuda_bf16.h>
#include <cstdint>

#define T_LEN 32768
#define HID   256
#define NI_   1024
#define OUT_  32
#define HSTR  1056   // padded h-buffer stride (bytes): half0 @0..512, half1 @528..1040

// ---------------- scratch (device globals: no allocation allowed) ----------------
__device__ float g_xg_f[(size_t)T_LEN * 1024];
__device__ float g_xg_b[(size_t)T_LEN * 1024];
__device__ float g_h0[(size_t)T_LEN * 512];
__device__ float g_h1[(size_t)T_LEN * 512];

// ---------------- device helpers ----------------
__device__ __forceinline__ unsigned long long ffma2(unsigned long long a,
                                                    unsigned long long b,
                                                    unsigned long long c) {
    unsigned long long d;
    asm("fma.rn.f32x2 %0, %1, %2, %3;" : "=l"(d) : "l"(a), "l"(b), "l"(c));
    return d;
}

__device__ __forceinline__ uint32_t smaddr(const void* p) {
    return (uint32_t)__cvta_generic_to_shared(p);
}
__device__ __forceinline__ void mbar_init(uint32_t a, uint32_t cnt) {
    asm volatile("mbarrier.init.shared.b64 [%0], %1;" :: "r"(a), "r"(cnt) : "memory");
}
__device__ __forceinline__ uint32_t mapa_sh(uint32_t a, uint32_t rank) {
    uint32_t r;
    asm("mapa.shared::cluster.u32 %0, %1, %2;" : "=r"(r) : "r"(a), "r"(rank));
    return r;
}
__device__ __forceinline__ void mbar_wait_cl(uint32_t addr, uint32_t parity) {
    asm volatile(
        "{\n\t.reg .pred P;\n"
        "LW_%=:\n\t"
        "mbarrier.try_wait.parity.acquire.cluster.shared::cta.b64 P, [%0], %1;\n\t"
        "@P bra LD_%=;\n\t"
        "bra LW_%=;\n"
        "LD_%=:\n\t}"
        :: "r"(addr), "r"(parity) : "memory");
}
__device__ __forceinline__ void cluster_sync_() {
    asm volatile("barrier.cluster.arrive.aligned;" ::: "memory");
    asm volatile("barrier.cluster.wait.aligned;" ::: "memory");
}

// =================================================================================
// Kernel 1: layer-0 input projection. xg[t][row] = x[t] . w_ih[row] + b_ih + b_hh
// =================================================================================
__global__ void __launch_bounds__(256) xg0_kernel(
    const float* __restrict__ Y, const float* __restrict__ dT,
    const float* __restrict__ w_f, const float* __restrict__ bi_f, const float* __restrict__ bh_f,
    const float* __restrict__ w_b, const float* __restrict__ bi_b, const float* __restrict__ bh_b,
    float* __restrict__ out_f, float* __restrict__ out_b)
{
    __shared__ float xs[32][64];
    __shared__ float ws[64][128];
    const float* w  = blockIdx.z ? w_b  : w_f;
    const float* bi = blockIdx.z ? bi_b : bi_f;
    const float* bh = blockIdx.z ? bh_b : bh_f;
    float* out      = blockIdx.z ? out_b : out_f;

    const int tid = threadIdx.x;
    const int tbase = blockIdx.y * 32;
    const int cbase = blockIdx.x * 128;

    for (int i = tid; i < 32 * 64; i += 256) {
        int tt = i >> 6, k = i & 63;
        int t = tbase + tt;
        xs[tt][k] = (k < 63) ? Y[(size_t)t * 63 + k] : dT[t];
    }
    for (int i = tid; i < 128 * 64; i += 256) {
        int c = i >> 6, k = i & 63;
        ws[k][c] = w[(size_t)(cbase + c) * 64 + k];
    }
    __syncthreads();

    const int c = tid & 127;
    const int tr0 = tid >> 7;
    const float bias = bi[cbase + c] + bh[cbase + c];
    for (int tt = tr0; tt < 32; tt += 2) {
        float acc = bias;
        #pragma unroll
        for (int k = 0; k < 64; k++) acc += xs[tt][k] * ws[k][c];
        out[(size_t)(tbase + tt) * 1024 + cbase + c] = acc;
    }
}

// =================================================================================
// Kernel 2: LSTM scan v4. 8-CTA cluster per direction (2 clusters, grid 16).
// Protocol = R5 (proven): per step, 8 warp leaders each push this CTA's 128-B
// slice to ONE peer + single release-arrive on the peer's double-buffered mbar
// (count 8). Gates = R6 (proven): warp-local shuffle reduce/gather, no warp0
// serialization, ONE __syncthreads per step. Dest h buffer padded (HSTR) so the
// MAC's half0/half1 reads hit different bank groups (conflict-free).
// =================================================================================
__global__ void __launch_bounds__(256, 1) lstm_scan_kernel(
    const float* __restrict__ xg_f, const float* __restrict__ xg_b,
    const float* __restrict__ whh_f, const float* __restrict__ whh_b,
    float* __restrict__ h_out)
{
    __shared__ __align__(16) unsigned char h_raw[2 * HSTR];  // padded, double buffered
    __shared__ __align__(16) float h_stage[32];              // this CTA's 32 h values
    __shared__ unsigned long long mbar[2];

    const int tid  = threadIdx.x;
    const int lane = tid & 31;
    const int wid  = tid >> 5;
    const int rank = blockIdx.x & 7;
    const int dir  = blockIdx.x >> 3;
    const float* xg  = dir ? xg_b  : xg_f;
    const float* whh = dir ? whh_b : whh_f;
    const int unit_base = rank * 32;

    const int q    = lane >> 1;      // pair 0..15
    const int half = lane & 1;
    const int gate = q >> 2;         // 0..3 (i,f,g,o)
    const int u    = q & 3;          // unit within warp
    const int ub4  = unit_base + 4 * wid;            // this warp's first unit
    const int row  = gate * 256 + ub4 + u;           // W_hh row

    // Load this thread's 128 weights (half row) as 64 f32x2 pairs.
    unsigned long long w[64];
    {
        const ulonglong2* wg = (const ulonglong2*)(whh + (size_t)row * 256 + half * 128);
        #pragma unroll
        for (int i = 0; i < 32; i++) {
            ulonglong2 v = wg[i];
            w[2 * i] = v.x; w[2 * i + 1] = v.y;
        }
    }

    for (int i = tid; i < 2 * HSTR / 4; i += 256) ((uint32_t*)h_raw)[i] = 0u;
    if (tid < 2) mbar_init(smaddr(&mbar[tid]), 8);   // 8 arrivals: one per source CTA
    __syncthreads();
    cluster_sync_();   // everything initialized before any remote traffic

    const uint32_t hb      = smaddr(h_raw);
    const uint32_t mb_base = smaddr(&mbar[0]);
    const uint32_t stg     = smaddr(h_stage);

    // Warp leader `wid` sends this CTA's 128-B slice to peer rank `wid`.
    // Slice byte offset inside the padded layout (slices never cross the pad).
    const uint32_t soff = (rank < 4) ? (uint32_t)(128 * rank)
                                     : (uint32_t)(528 + 128 * (rank - 4));
    uint32_t peer_h = 0, peer_mb = 0;
    if (lane == 0) {
        peer_h  = mapa_sh(hb, (uint32_t)wid) + soff;
        peer_mb = mapa_sh(mb_base, (uint32_t)wid);
    }

    // reader base: half0 at +0, half1 at +528 (different bank group)
    const uint32_t rd_base = hb + (half ? 528u : 0u);

    const int t0 = dir ? (T_LEN - 1) : 0;
    const int dt = dir ? -1 : 1;

    float c_state = 0.f;   // valid in lanes 0..3
    float xg_cur = 0.f, xg_nxt = 0.f;
    if (!half) {
        xg_cur = __ldg(&xg[(size_t)t0 * 1024 + row]);
        xg_nxt = __ldg(&xg[(size_t)(t0 + dt) * 1024 + row]);
    }
    int ph0 = 0, ph1 = 0;

    for (int s = 0; s < T_LEN; s++) {
        const int t = t0 + s * dt;
        const int buf = s & 1;
        const int nb  = buf ^ 1;

        // prefetch xg for step s+2 before blocking
        float xg_n2 = 0.f;
        if (!half && (s + 2 < T_LEN))
            xg_n2 = __ldg(&xg[(size_t)(t + 2 * dt) * 1024 + row]);

        if (s > 0) {
            uint32_t mb = mb_base + 8u * (uint32_t)buf;
            int par = buf ? ph1 : ph0;
            if (lane == 0) mbar_wait_cl(mb, (uint32_t)par);  // single poller per warp
            __syncwarp();
            if (buf) ph1 ^= 1; else ph0 ^= 1;
        }

        // MAC: 32 conflict-free LDS.128 + 64 FFMA2, 4 accumulator chains
        const uint32_t ra = rd_base + (uint32_t)buf * (uint32_t)HSTR;
        unsigned long long acc0 = 0ULL, acc1 = 0ULL, acc2 = 0ULL, acc3 = 0ULL;
        #pragma unroll
        for (int i = 0; i < 8; i++) {
            ulonglong2 ha  = *(const ulonglong2*)(h_raw + (ra - hb) + 64u * i);
            ulonglong2 hb2 = *(const ulonglong2*)(h_raw + (ra - hb) + 64u * i + 16u);
            ulonglong2 hc  = *(const ulonglong2*)(h_raw + (ra - hb) + 64u * i + 32u);
            ulonglong2 hd  = *(const ulonglong2*)(h_raw + (ra - hb) + 64u * i + 48u);
            acc0 = ffma2(w[8 * i + 0], ha.x,  acc0);
            acc1 = ffma2(w[8 * i + 1], ha.y,  acc1);
            acc2 = ffma2(w[8 * i + 2], hb2.x, acc2);
            acc3 = ffma2(w[8 * i + 3], hb2.y, acc3);
            acc0 = ffma2(w[8 * i + 4], hc.x,  acc0);
            acc1 = ffma2(w[8 * i + 5], hc.y,  acc1);
            acc2 = ffma2(w[8 * i + 6], hd.x,  acc2);
            acc3 = ffma2(w[8 * i + 7], hd.y,  acc3);
        }
        float2 a0 = *(float2*)&acc0, a1 = *(float2*)&acc1;
        float2 a2 = *(float2*)&acc2, a3 = *(float2*)&acc3;
        float sum = ((a0.x + a0.y) + (a1.x + a1.y)) + ((a2.x + a2.y) + (a3.x + a3.y));
        sum += __shfl_xor_sync(0xffffffffu, sum, 1);   // combine the two row halves
        if (!half) sum += xg_cur;                       // full preact on even lanes

        // gather the 4 gate preacts of unit (lane&3) from even lanes
        const int uu = lane & 3;
        float iv = __shfl_sync(0xffffffffu, sum, 2 * uu);
        float fv = __shfl_sync(0xffffffffu, sum, 8 + 2 * uu);
        float gv = __shfl_sync(0xffffffffu, sum, 16 + 2 * uu);
        float ov = __shfl_sync(0xffffffffu, sum, 24 + 2 * uu);

        // gates (meaningful in lanes 0..3; other lanes compute harmless duplicates)
        float ei = __expf(-iv), ef = __expf(-fv), eo = __expf(-ov);
        float eg = __expf(-2.f * fabsf(gv));
        float si = __fdividef(1.f, 1.f + ei);
        float sf = __fdividef(1.f, 1.f + ef);
        float so = __fdividef(1.f, 1.f + eo);
        float tg = copysignf(__fdividef(1.f - eg, 1.f + eg), gv);
        c_state = sf * c_state + si * tg;
        float ec = __expf(-2.f * fabsf(c_state));
        float tc = copysignf(__fdividef(1.f - ec, 1.f + ec), c_state);
        float h = so * tc;

        if (lane < 4) {
            h_stage[4 * wid + lane] = h;
            h_out[(size_t)t * 512 + dir * 256 + ub4 + lane] = h;
        }
        __syncthreads();   // h_stage complete across all 8 warps

        // 8 warp leaders: push 128-B slice to peer `wid`, then single release-arrive.
        if (lane == 0) {
            const uint32_t dst = peer_h + (uint32_t)nb * (uint32_t)HSTR;
            #pragma unroll
            for (int i = 0; i < 8; i++) {
                uint32_t v0, v1, v2, v3;
                asm("ld.shared.v4.b32 {%0,%1,%2,%3}, [%4];"
                    : "=r"(v0), "=r"(v1), "=r"(v2), "=r"(v3)
                    : "r"(stg + (uint32_t)(i * 16)));
                asm volatile("st.shared::cluster.v4.b32 [%0], {%1,%2,%3,%4};"
                             :: "r"(dst + (uint32_t)(i * 16)),
                                "r"(v0), "r"(v1), "r"(v2), "r"(v3) : "memory");
            }
            asm volatile("mbarrier.arrive.release.cluster.shared::cluster.b64 _, [%0];"
                         :: "r"(peer_mb + 8u * (uint32_t)nb) : "memory");
        }
        xg_cur = xg_nxt;
        xg_nxt = xg_n2;
    }
    cluster_sync_();   // don't exit while peers' remote stores may target our SMEM
}

// =================================================================================
// Kernel 3: layer-1 input projection GEMM. BM=64, BN=64, BK=16, 256 threads.
// =================================================================================
__global__ void __launch_bounds__(256) xg1_gemm(
    const float* __restrict__ A,
    const float* __restrict__ Wf, const float* __restrict__ Wb,
    const float* __restrict__ bif, const float* __restrict__ bhf,
    const float* __restrict__ bib, const float* __restrict__ bhb,
    float* __restrict__ outf, float* __restrict__ outb)
{
    const float* W  = blockIdx.z ? Wb  : Wf;
    const float* bi = blockIdx.z ? bib : bif;
    const float* bh = blockIdx.z ? bhb : bhf;
    float* out      = blockIdx.z ? outb : outf;

    __shared__ float As[16][68];
    __shared__ float Bs[16][68];

    const int tid = threadIdx.x;
    const int tm = blockIdx.y * 64;
    const int cn = blockIdx.x * 64;
    const int tx = tid & 15;
    const int ty = tid >> 4;

    const int la_t = tid >> 2;
    const int la_k = (tid & 3) * 4;

    float acc[4][4] = {};

    for (int k0 = 0; k0 < 512; k0 += 16) {
        float4 av = *(const float4*)&A[(size_t)(tm + la_t) * 512 + k0 + la_k];
        float4 wv = *(const float4*)&W[(size_t)(cn + la_t) * 512 + k0 + la_k];
        __syncthreads();
        As[la_k + 0][la_t] = av.x; As[la_k + 1][la_t] = av.y;
        As[la_k + 2][la_t] = av.z; As[la_k + 3][la_t] = av.w;
        Bs[la_k + 0][la_t] = wv.x; Bs[la_k + 1][la_t] = wv.y;
        Bs[la_k + 2][la_t] = wv.z; Bs[la_k + 3][la_t] = wv.w;
        __syncthreads();
        #pragma unroll
        for (int k = 0; k < 16; k++) {
            float a[4], b[4];
            #pragma unroll
            for (int i = 0; i < 4; i++) a[i] = As[k][ty * 4 + i];
            #pragma unroll
            for (int j = 0; j < 4; j++) b[j] = Bs[k][tx * 4 + j];
            #pragma unroll
            for (int i = 0; i < 4; i++)
                #pragma unroll
                for (int j = 0; j < 4; j++)
                    acc[i][j] += a[i] * b[j];
        }
    }

    float bias[4];
    #pragma unroll
    for (int j = 0; j < 4; j++)
        bias[j] = bi[cn + tx * 4 + j] + bh[cn + tx * 4 + j];
    #pragma unroll
    for (int i = 0; i < 4; i++)
        #pragma unroll
        for (int j = 0; j < 4; j++)
            out[(size_t)(tm + ty * 4 + i) * 1024 + cn + tx * 4 + j] = acc[i][j] + bias[j];
}

// =================================================================================
// Kernel 4: FC at inducing points + split output.
// =================================================================================
__global__ void __launch_bounds__(64) fc_gather_kernel(
    const float* __restrict__ h1, const int* __restrict__ idx,
    const float* __restrict__ fc, float* __restrict__ out)
{
    __shared__ float hrow[512];
    const int b = blockIdx.x;
    const int t = idx[b];
    const int tid = threadIdx.x;
    for (int i = tid; i < 512; i += 64) hrow[i] = h1[(size_t)t * 512 + i];
    __syncthreads();
    float acc = 0.f;
    #pragma unroll 8
    for (int k = 0; k < 512; k++) acc += hrow[k] * fc[(size_t)k * 64 + tid];
    if (tid < 32) out[b * 32 + tid] = acc;
    else          out[NI_ * OUT_ + b * 32 + (tid - 32)] = acc;
}

// =================================================================================
// Launch
// =================================================================================
extern "C" void kernel_launch(void* const* d_in, const int* in_sizes, int n_in,
                              void* d_out, int out_size) {
    const float* Y        = (const float*)d_in[0];
    const float* dT       = (const float*)d_in[1];
    const int*   induce   = (const int*)  d_in[2];
    const float* w_ih_l0f = (const float*)d_in[3];
    const float* w_hh_l0f = (const float*)d_in[4];
    const float* b_ih_l0f = (const float*)d_in[5];
    const float* b_hh_l0f = (const float*)d_in[6];
    const float* w_ih_l0b = (const float*)d_in[7];
    const float* w_hh_l0b = (const float*)d_in[8];
    const float* b_ih_l0b = (const float*)d_in[9];
    const float* b_hh_l0b = (const float*)d_in[10];
    const float* w_ih_l1f = (const float*)d_in[11];
    const float* w_hh_l1f = (const float*)d_in[12];
    const float* b_ih_l1f = (const float*)d_in[13];
    const float* b_hh_l1f = (const float*)d_in[14];
    const float* w_ih_l1b = (const float*)d_in[15];
    const float* w_hh_l1b = (const float*)d_in[16];
    const float* b_ih_l1b = (const float*)d_in[17];
    const float* b_hh_l1b = (const float*)d_in[18];
    const float* fc_w     = (const float*)d_in[19];
    float* out = (float*)d_out;

    float *xg_f, *xg_b, *h0, *h1;
    cudaGetSymbolAddress((void**)&xg_f, g_xg_f);
    cudaGetSymbolAddress((void**)&xg_b, g_xg_b);
    cudaGetSymbolAddress((void**)&h0, g_h0);
    cudaGetSymbolAddress((void**)&h1, g_h1);

    // 1) layer-0 gate preactivations
    xg0_kernel<<<dim3(8, T_LEN / 32, 2), 256>>>(
        Y, dT,
        w_ih_l0f, b_ih_l0f, b_hh_l0f,
        w_ih_l0b, b_ih_l0b, b_hh_l0b,
        xg_f, xg_b);

    // cluster launch config for the scan
    cudaLaunchConfig_t cfg = {};
    cfg.gridDim  = dim3(16, 1, 1);
    cfg.blockDim = dim3(256, 1, 1);
    cfg.dynamicSmemBytes = 0;
    cfg.stream = 0;
    cudaLaunchAttribute attr[1];
    attr[0].id = cudaLaunchAttributeClusterDimension;
    attr[0].val.clusterDim.x = 8;
    attr[0].val.clusterDim.y = 1;
    attr[0].val.clusterDim.z = 1;
    cfg.attrs = attr;
    cfg.numAttrs = 1;

    // 2) layer-0 scan
    cudaLaunchKernelEx(&cfg, lstm_scan_kernel,
                       (const float*)xg_f, (const float*)xg_b,
                       w_hh_l0f, w_hh_l0b, h0);

    // 3) layer-1 gate preactivations (reuse xg buffers)
    xg1_gemm<<<dim3(16, T_LEN / 64, 2), 256>>>(
        (const float*)h0,
        w_ih_l1f, w_ih_l1b,
        b_ih_l1f, b_hh_l1f, b_ih_l1b, b_hh_l1b,
        xg_f, xg_b);

    // 4) layer-1 scan
    cudaLaunchKernelEx(&cfg, lstm_scan_kernel,
                       (const float*)xg_f, (const float*)xg_b,
                       w_hh_l1f, w_hh_l1b, h1);

    // 5) FC + gather
    fc_gather_kernel<<<NI_, 64>>>((const float*)h1, induce, fc_w, out);
}

// round 8
// speedup vs baseline: 4.0403x; 1.7046x over previous
#include <cuda_runtime.h>
#include <cuda_bf16.h>
#include <cstdint>

#define T_LEN 32768
#define HID   256
#define NI_   1024
#define OUT_  32
#define HSTR  1056   // padded h-buffer stride (bytes): half0 @0..512, half1 @528..1040

// ---------------- scratch (device globals: no allocation allowed) ----------------
__device__ float g_xg_f[(size_t)T_LEN * 1024];
__device__ float g_xg_b[(size_t)T_LEN * 1024];
__device__ float g_h0[(size_t)T_LEN * 512];
__device__ float g_h1[(size_t)T_LEN * 512];

// ---------------- device helpers ----------------
__device__ __forceinline__ unsigned long long ffma2(unsigned long long a,
                                                    unsigned long long b,
                                                    unsigned long long c) {
    unsigned long long d;
    asm("fma.rn.f32x2 %0, %1, %2, %3;" : "=l"(d) : "l"(a), "l"(b), "l"(c));
    return d;
}

__device__ __forceinline__ uint32_t smaddr(const void* p) {
    return (uint32_t)__cvta_generic_to_shared(p);
}
__device__ __forceinline__ void mbar_init(uint32_t a, uint32_t cnt) {
    asm volatile("mbarrier.init.shared.b64 [%0], %1;" :: "r"(a), "r"(cnt) : "memory");
}
__device__ __forceinline__ void mbar_expect_tx(uint32_t a, uint32_t bytes) {
    asm volatile("mbarrier.arrive.expect_tx.shared.b64 _, [%0], %1;"
                 :: "r"(a), "r"(bytes) : "memory");
}
__device__ __forceinline__ uint32_t mapa_sh(uint32_t a, uint32_t rank) {
    uint32_t r;
    asm("mapa.shared::cluster.u32 %0, %1, %2;" : "=r"(r) : "r"(a), "r"(rank));
    return r;
}
__device__ __forceinline__ void mbar_wait_cl(uint32_t addr, uint32_t parity) {
    asm volatile(
        "{\n\t.reg .pred P;\n"
        "LW_%=:\n\t"
        "mbarrier.try_wait.parity.acquire.cluster.shared::cta.b64 P, [%0], %1;\n\t"
        "@P bra LD_%=;\n\t"
        "bra LW_%=;\n"
        "LD_%=:\n\t}"
        :: "r"(addr), "r"(parity) : "memory");
}
__device__ __forceinline__ void cluster_sync_() {
    asm volatile("barrier.cluster.arrive.aligned;" ::: "memory");
    asm volatile("barrier.cluster.wait.aligned;" ::: "memory");
}

// =================================================================================
// Kernel 1: layer-0 input projection. xg[t][row] = x[t] . w_ih[row] + b_ih + b_hh
// =================================================================================
__global__ void __launch_bounds__(256) xg0_kernel(
    const float* __restrict__ Y, const float* __restrict__ dT,
    const float* __restrict__ w_f, const float* __restrict__ bi_f, const float* __restrict__ bh_f,
    const float* __restrict__ w_b, const float* __restrict__ bi_b, const float* __restrict__ bh_b,
    float* __restrict__ out_f, float* __restrict__ out_b)
{
    __shared__ float xs[32][64];
    __shared__ float ws[64][128];
    const float* w  = blockIdx.z ? w_b  : w_f;
    const float* bi = blockIdx.z ? bi_b : bi_f;
    const float* bh = blockIdx.z ? bh_b : bh_f;
    float* out      = blockIdx.z ? out_b : out_f;

    const int tid = threadIdx.x;
    const int tbase = blockIdx.y * 32;
    const int cbase = blockIdx.x * 128;

    for (int i = tid; i < 32 * 64; i += 256) {
        int tt = i >> 6, k = i & 63;
        int t = tbase + tt;
        xs[tt][k] = (k < 63) ? Y[(size_t)t * 63 + k] : dT[t];
    }
    for (int i = tid; i < 128 * 64; i += 256) {
        int c = i >> 6, k = i & 63;
        ws[k][c] = w[(size_t)(cbase + c) * 64 + k];
    }
    __syncthreads();

    const int c = tid & 127;
    const int tr0 = tid >> 7;
    const float bias = bi[cbase + c] + bh[cbase + c];
    for (int tt = tr0; tt < 32; tt += 2) {
        float acc = bias;
        #pragma unroll
        for (int k = 0; k < 64; k++) acc += xs[tt][k] * ws[k][c];
        out[(size_t)(tbase + tt) * 1024 + cbase + c] = acc;
    }
}

// =================================================================================
// Kernel 2: LSTM scan v5. 8-CTA cluster per direction (2 clusters, grid 16).
// Comms: per step, each of 8 warp leaders issues ONE cp.async.bulk (128 B) of
// this CTA's h slice into one peer, with mbarrier::complete_tx at the peer.
// Receiver mbar (count 1) completes on local arrive.expect_tx(1024) + 8x128 B.
// expect_tx is issued by tid0 right after its wait for that buffer -> provably
// before any peer can send into that phase. h_stage is double-buffered: slot b's
// bulk read at step s is provably done by s+2 (peers' waits chain through it).
// fence.proxy.async orders the generic STS before the async-proxy bulk read.
// =================================================================================
__global__ void __launch_bounds__(256, 1) lstm_scan_kernel(
    const float* __restrict__ xg_f, const float* __restrict__ xg_b,
    const float* __restrict__ whh_f, const float* __restrict__ whh_b,
    float* __restrict__ h_out)
{
    __shared__ __align__(16) unsigned char h_raw[2 * HSTR];  // padded, double buffered
    __shared__ __align__(16) float h_stage[2][32];           // double-buffered stage
    __shared__ unsigned long long mbar[2];

    const int tid  = threadIdx.x;
    const int lane = tid & 31;
    const int wid  = tid >> 5;
    const int rank = blockIdx.x & 7;
    const int dir  = blockIdx.x >> 3;
    const float* xg  = dir ? xg_b  : xg_f;
    const float* whh = dir ? whh_b : whh_f;
    const int unit_base = rank * 32;

    const int q    = lane >> 1;      // pair 0..15
    const int half = lane & 1;
    const int gate = q >> 2;         // 0..3 (i,f,g,o)
    const int u    = q & 3;          // unit within warp
    const int ub4  = unit_base + 4 * wid;            // this warp's first unit
    const int row  = gate * 256 + ub4 + u;           // W_hh row

    // Load this thread's 128 weights (half row) as 64 f32x2 pairs.
    unsigned long long w[64];
    {
        const ulonglong2* wg = (const ulonglong2*)(whh + (size_t)row * 256 + half * 128);
        #pragma unroll
        for (int i = 0; i < 32; i++) {
            ulonglong2 v = wg[i];
            w[2 * i] = v.x; w[2 * i + 1] = v.y;
        }
    }

    for (int i = tid; i < 2 * HSTR / 4; i += 256) ((uint32_t*)h_raw)[i] = 0u;
    if (tid < 2) mbar_init(smaddr(&mbar[tid]), 1);   // 1 arrival: the local expect_tx
    __syncthreads();
    const uint32_t hb      = smaddr(h_raw);
    const uint32_t mb_base = smaddr(&mbar[0]);
    const uint32_t stg     = smaddr(&h_stage[0][0]);
    if (tid == 0) {
        mbar_expect_tx(mb_base, 1024);       // covers refill of buf0 (used at s=2)
        mbar_expect_tx(mb_base + 8u, 1024);  // covers refill of buf1 (used at s=1)
    }
    __syncthreads();
    cluster_sync_();   // everything initialized before any remote traffic

    // Warp leader `wid` sends this CTA's 128-B slice to peer rank `wid`.
    // Slice byte offset inside the padded layout (slices never cross the pad).
    const uint32_t soff = (rank < 4) ? (uint32_t)(128 * rank)
                                     : (uint32_t)(528 + 128 * (rank - 4));
    uint32_t peer_h = 0, peer_mb = 0;
    if (lane == 0) {
        peer_h  = mapa_sh(hb, (uint32_t)wid) + soff;
        peer_mb = mapa_sh(mb_base, (uint32_t)wid);
    }

    // reader base: half0 at +0, half1 at +528 (different bank group)
    const uint32_t rd_base = hb + (half ? 528u : 0u);

    const int t0 = dir ? (T_LEN - 1) : 0;
    const int dt = dir ? -1 : 1;

    float c_state = 0.f;   // valid in lanes 0..3
    float xg_cur = 0.f, xg_nxt = 0.f;
    if (!half) {
        xg_cur = __ldg(&xg[(size_t)t0 * 1024 + row]);
        xg_nxt = __ldg(&xg[(size_t)(t0 + dt) * 1024 + row]);
    }
    int ph0 = 0, ph1 = 0;

    for (int s = 0; s < T_LEN; s++) {
        const int t = t0 + s * dt;
        const int buf = s & 1;
        const int nb  = buf ^ 1;

        // prefetch xg for step s+2 before blocking
        float xg_n2 = 0.f;
        if (!half && (s + 2 < T_LEN))
            xg_n2 = __ldg(&xg[(size_t)(t + 2 * dt) * 1024 + row]);

        if (s > 0) {
            uint32_t mb = mb_base + 8u * (uint32_t)buf;
            int par = buf ? ph1 : ph0;
            if (lane == 0) {
                mbar_wait_cl(mb, (uint32_t)par);     // single poller per warp
                if (tid == 0) mbar_expect_tx(mb, 1024);  // next phase of this buf
            }
            __syncwarp();
            if (buf) ph1 ^= 1; else ph0 ^= 1;
        }

        // MAC: 32 conflict-free LDS.128 + 64 FFMA2, 4 accumulator chains
        const uint32_t ra = rd_base + (uint32_t)buf * (uint32_t)HSTR;
        unsigned long long acc0 = 0ULL, acc1 = 0ULL, acc2 = 0ULL, acc3 = 0ULL;
        #pragma unroll
        for (int i = 0; i < 8; i++) {
            ulonglong2 ha  = *(const ulonglong2*)(h_raw + (ra - hb) + 64u * i);
            ulonglong2 hb2 = *(const ulonglong2*)(h_raw + (ra - hb) + 64u * i + 16u);
            ulonglong2 hc  = *(const ulonglong2*)(h_raw + (ra - hb) + 64u * i + 32u);
            ulonglong2 hd  = *(const ulonglong2*)(h_raw + (ra - hb) + 64u * i + 48u);
            acc0 = ffma2(w[8 * i + 0], ha.x,  acc0);
            acc1 = ffma2(w[8 * i + 1], ha.y,  acc1);
            acc2 = ffma2(w[8 * i + 2], hb2.x, acc2);
            acc3 = ffma2(w[8 * i + 3], hb2.y, acc3);
            acc0 = ffma2(w[8 * i + 4], hc.x,  acc0);
            acc1 = ffma2(w[8 * i + 5], hc.y,  acc1);
            acc2 = ffma2(w[8 * i + 6], hd.x,  acc2);
            acc3 = ffma2(w[8 * i + 7], hd.y,  acc3);
        }
        float2 a0 = *(float2*)&acc0, a1 = *(float2*)&acc1;
        float2 a2 = *(float2*)&acc2, a3 = *(float2*)&acc3;
        float sum = ((a0.x + a0.y) + (a1.x + a1.y)) + ((a2.x + a2.y) + (a3.x + a3.y));
        sum += __shfl_xor_sync(0xffffffffu, sum, 1);   // combine the two row halves
        if (!half) sum += xg_cur;                       // full preact on even lanes

        // gather the 4 gate preacts of unit (lane&3) from even lanes
        const int uu = lane & 3;
        float iv = __shfl_sync(0xffffffffu, sum, 2 * uu);
        float fv = __shfl_sync(0xffffffffu, sum, 8 + 2 * uu);
        float gv = __shfl_sync(0xffffffffu, sum, 16 + 2 * uu);
        float ov = __shfl_sync(0xffffffffu, sum, 24 + 2 * uu);

        // gates (meaningful in lanes 0..3; other lanes compute harmless duplicates)
        float ei = __expf(-iv), ef = __expf(-fv), eo = __expf(-ov);
        float eg = __expf(-2.f * fabsf(gv));
        float si = __fdividef(1.f, 1.f + ei);
        float sf = __fdividef(1.f, 1.f + ef);
        float so = __fdividef(1.f, 1.f + eo);
        float tg = copysignf(__fdividef(1.f - eg, 1.f + eg), gv);
        c_state = sf * c_state + si * tg;
        float ec = __expf(-2.f * fabsf(c_state));
        float tc = copysignf(__fdividef(1.f - ec, 1.f + ec), c_state);
        float h = so * tc;

        if (lane < 4) {
            h_stage[buf][4 * wid + lane] = h;
            h_out[(size_t)t * 512 + dir * 256 + ub4 + lane] = h;
        }
        __syncthreads();   // h_stage[buf] complete across all 8 warps

        // 8 warp leaders: ONE 128-B bulk copy to peer `wid` with complete_tx.
        if (lane == 0 && (s + 1 < T_LEN)) {
            asm volatile("fence.proxy.async.shared::cta;" ::: "memory");
            const uint32_t dst = peer_h + (uint32_t)nb * (uint32_t)HSTR;
            const uint32_t rmb = peer_mb + 8u * (uint32_t)nb;
            const uint32_t src = stg + (uint32_t)buf * 128u;
            asm volatile(
                "cp.async.bulk.shared::cluster.shared::cta.mbarrier::complete_tx::bytes "
                "[%0], [%1], %2, [%3];"
                :: "r"(dst), "r"(src), "r"(128u), "r"(rmb) : "memory");
        }
        xg_cur = xg_nxt;
        xg_nxt = xg_n2;
    }
    cluster_sync_();   // don't exit while peers' bulk writes may target our SMEM
}

// =================================================================================
// Kernel 3: layer-1 input projection GEMM. BM=64, BN=64, BK=16, 256 threads.
// =================================================================================
__global__ void __launch_bounds__(256) xg1_gemm(
    const float* __restrict__ A,
    const float* __restrict__ Wf, const float* __restrict__ Wb,
    const float* __restrict__ bif, const float* __restrict__ bhf,
    const float* __restrict__ bib, const float* __restrict__ bhb,
    float* __restrict__ outf, float* __restrict__ outb)
{
    const float* W  = blockIdx.z ? Wb  : Wf;
    const float* bi = blockIdx.z ? bib : bif;
    const float* bh = blockIdx.z ? bhb : bhf;
    float* out      = blockIdx.z ? outb : outf;

    __shared__ float As[16][68];
    __shared__ float Bs[16][68];

    const int tid = threadIdx.x;
    const int tm = blockIdx.y * 64;
    const int cn = blockIdx.x * 64;
    const int tx = tid & 15;
    const int ty = tid >> 4;

    const int la_t = tid >> 2;
    const int la_k = (tid & 3) * 4;

    float acc[4][4] = {};

    for (int k0 = 0; k0 < 512; k0 += 16) {
        float4 av = *(const float4*)&A[(size_t)(tm + la_t) * 512 + k0 + la_k];
        float4 wv = *(const float4*)&W[(size_t)(cn + la_t) * 512 + k0 + la_k];
        __syncthreads();
        As[la_k + 0][la_t] = av.x; As[la_k + 1][la_t] = av.y;
        As[la_k + 2][la_t] = av.z; As[la_k + 3][la_t] = av.w;
        Bs[la_k + 0][la_t] = wv.x; Bs[la_k + 1][la_t] = wv.y;
        Bs[la_k + 2][la_t] = wv.z; Bs[la_k + 3][la_t] = wv.w;
        __syncthreads();
        #pragma unroll
        for (int k = 0; k < 16; k++) {
            float a[4], b[4];
            #pragma unroll
            for (int i = 0; i < 4; i++) a[i] = As[k][ty * 4 + i];
            #pragma unroll
            for (int j = 0; j < 4; j++) b[j] = Bs[k][tx * 4 + j];
            #pragma unroll
            for (int i = 0; i < 4; i++)
                #pragma unroll
                for (int j = 0; j < 4; j++)
                    acc[i][j] += a[i] * b[j];
        }
    }

    float bias[4];
    #pragma unroll
    for (int j = 0; j < 4; j++)
        bias[j] = bi[cn + tx * 4 + j] + bh[cn + tx * 4 + j];
    #pragma unroll
    for (int i = 0; i < 4; i++)
        #pragma unroll
        for (int j = 0; j < 4; j++)
            out[(size_t)(tm + ty * 4 + i) * 1024 + cn + tx * 4 + j] = acc[i][j] + bias[j];
}

// =================================================================================
// Kernel 4: FC at inducing points + split output.
// =================================================================================
__global__ void __launch_bounds__(64) fc_gather_kernel(
    const float* __restrict__ h1, const int* __restrict__ idx,
    const float* __restrict__ fc, float* __restrict__ out)
{
    __shared__ float hrow[512];
    const int b = blockIdx.x;
    const int t = idx[b];
    const int tid = threadIdx.x;
    for (int i = tid; i < 512; i += 64) hrow[i] = h1[(size_t)t * 512 + i];
    __syncthreads();
    float acc = 0.f;
    #pragma unroll 8
    for (int k = 0; k < 512; k++) acc += hrow[k] * fc[(size_t)k * 64 + tid];
    if (tid < 32) out[b * 32 + tid] = acc;
    else          out[NI_ * OUT_ + b * 32 + (tid - 32)] = acc;
}

// =================================================================================
// Launch
// =================================================================================
extern "C" void kernel_launch(void* const* d_in, const int* in_sizes, int n_in,
                              void* d_out, int out_size) {
    const float* Y        = (const float*)d_in[0];
    const float* dT       = (const float*)d_in[1];
    const int*   induce   = (const int*)  d_in[2];
    const float* w_ih_l0f = (const float*)d_in[3];
    const float* w_hh_l0f = (const float*)d_in[4];
    const float* b_ih_l0f = (const float*)d_in[5];
    const float* b_hh_l0f = (const float*)d_in[6];
    const float* w_ih_l0b = (const float*)d_in[7];
    const float* w_hh_l0b = (const float*)d_in[8];
    const float* b_ih_l0b = (const float*)d_in[9];
    const float* b_hh_l0b = (const float*)d_in[10];
    const float* w_ih_l1f = (const float*)d_in[11];
    const float* w_hh_l1f = (const float*)d_in[12];
    const float* b_ih_l1f = (const float*)d_in[13];
    const float* b_hh_l1f = (const float*)d_in[14];
    const float* w_ih_l1b = (const float*)d_in[15];
    const float* w_hh_l1b = (const float*)d_in[16];
    const float* b_ih_l1b = (const float*)d_in[17];
    const float* b_hh_l1b = (const float*)d_in[18];
    const float* fc_w     = (const float*)d_in[19];
    float* out = (float*)d_out;

    float *xg_f, *xg_b, *h0, *h1;
    cudaGetSymbolAddress((void**)&xg_f, g_xg_f);
    cudaGetSymbolAddress((void**)&xg_b, g_xg_b);
    cudaGetSymbolAddress((void**)&h0, g_h0);
    cudaGetSymbolAddress((void**)&h1, g_h1);

    // 1) layer-0 gate preactivations
    xg0_kernel<<<dim3(8, T_LEN / 32, 2), 256>>>(
        Y, dT,
        w_ih_l0f, b_ih_l0f, b_hh_l0f,
        w_ih_l0b, b_ih_l0b, b_hh_l0b,
        xg_f, xg_b);

    // cluster launch config for the scan
    cudaLaunchConfig_t cfg = {};
    cfg.gridDim  = dim3(16, 1, 1);
    cfg.blockDim = dim3(256, 1, 1);
    cfg.dynamicSmemBytes = 0;
    cfg.stream = 0;
    cudaLaunchAttribute attr[1];
    attr[0].id = cudaLaunchAttributeClusterDimension;
    attr[0].val.clusterDim.x = 8;
    attr[0].val.clusterDim.y = 1;
    attr[0].val.clusterDim.z = 1;
    cfg.attrs = attr;
    cfg.numAttrs = 1;

    // 2) layer-0 scan
    cudaLaunchKernelEx(&cfg, lstm_scan_kernel,
                       (const float*)xg_f, (const float*)xg_b,
                       w_hh_l0f, w_hh_l0b, h0);

    // 3) layer-1 gate preactivations (reuse xg buffers)
    xg1_gemm<<<dim3(16, T_LEN / 64, 2), 256>>>(
        (const float*)h0,
        w_ih_l1f, w_ih_l1b,
        b_ih_l1f, b_hh_l1f, b_ih_l1b, b_hh_l1b,
        xg_f, xg_b);

    // 4) layer-1 scan
    cudaLaunchKernelEx(&cfg, lstm_scan_kernel,
                       (const float*)xg_f, (const float*)xg_b,
                       w_hh_l1f, w_hh_l1b, h1);

    // 5) FC + gather
    fc_gather_kernel<<<NI_, 64>>>((const float*)h1, induce, fc_w, out);
}